// round 11
// baseline (speedup 1.0000x reference)
#include <cuda_runtime.h>

typedef unsigned long long u64;
struct uu2 { u64 a, b; };

// ---------------- packed weights (consumption order, one constant blob) ----------------
//   [0    ..192 )  w12p[(ci*3+k)*8  + co]
//   [192  ..576 )  w21p[(ci*3+k)*16 + co]
//   [576  ..1344)  w22p[(ci*3+k)*16 + co]
//   [1344 ..3648)  Wlp [(t2*16+ch)*24 + o]   (feature r = t2*16+ch maps to f = ch*6+t2)
//   [3648 ..3672)  w11p[k*8 + co]
//   [3672 ..3680)  b11  [3680..3688) b12  [3688..3704) b21
//   [3704 ..3720)  b22  [3720..3744) bl
#define PACKN 3744
__device__ __align__(16) float g_pack[PACKN];
__constant__ __align__(16) float c_pack[PACKN];

// p2 scratch [feature r][sample]
#define MAXN 131072
__device__ float g_p2[96 * MAXN];

__device__ __forceinline__ u64 pk2(float lo, float hi) {
    u64 r; asm("mov.b64 %0,{%1,%2};" : "=l"(r) : "f"(lo), "f"(hi)); return r;
}
__device__ __forceinline__ float2 upk2(u64 v) {
    float2 f; asm("mov.b64 {%0,%1},%2;" : "=f"(f.x), "=f"(f.y) : "l"(v)); return f;
}
__device__ __forceinline__ u64 ffma2(u64 a, u64 b, u64 c) {
    u64 d; asm("fma.rn.f32x2 %0,%1,%2,%3;" : "=l"(d) : "l"(a), "l"(b), "l"(c)); return d;
}
__device__ __forceinline__ uu2 cpk4(int idx) {          // LDC.128 (idx multiple of 4)
    ulonglong2 v = *reinterpret_cast<const ulonglong2*>(&c_pack[idx]);
    uu2 r; r.a = v.x; r.b = v.y; return r;
}

__global__ void repack_kernel(
    const float* __restrict__ w11, const float* __restrict__ b11,
    const float* __restrict__ w12, const float* __restrict__ b12,
    const float* __restrict__ w21, const float* __restrict__ b21,
    const float* __restrict__ w22, const float* __restrict__ b22,
    const float* __restrict__ Wl,  const float* __restrict__ bl)
{
    int gtid = blockIdx.x * 256 + threadIdx.x;
    int stride = gridDim.x * 256;
    for (int i = gtid; i < 192;  i += stride) g_pack[i]       = w12[(i & 7)  * 24 + (i >> 3)];
    for (int i = gtid; i < 384;  i += stride) g_pack[192 + i] = w21[(i & 15) * 24 + (i >> 4)];
    for (int i = gtid; i < 768;  i += stride) g_pack[576 + i] = w22[(i & 15) * 48 + (i >> 4)];
    for (int i = gtid; i < 2304; i += stride) {
        int o = i % 24; int r = i / 24;
        g_pack[1344 + i] = Wl[o * 96 + (r & 15) * 6 + (r >> 4)];
    }
    if (gtid < 24) g_pack[3648 + gtid] = w11[(gtid & 7) * 3 + (gtid >> 3)];
    if (gtid < 8)  g_pack[3672 + gtid] = b11[gtid];
    if (gtid < 8)  g_pack[3680 + gtid] = b12[gtid];
    if (gtid < 16) g_pack[3688 + gtid] = b21[gtid];
    if (gtid < 16) g_pack[3704 + gtid] = b22[gtid];
    if (gtid < 24) g_pack[3720 + gtid] = bl[gtid];
}

#define P1_STRIDE 128
#define SMEM_BYTES (96 * 128 * 4)

// process one sample end-to-end (conv stages), p1 via per-thread smem column
__device__ __forceinline__ void process_sample(const float* __restrict__ x,
                                               float* __restrict__ p1s, int s, int n)
{
    // ---- input sample ----
    float xv[24];
    {
        const float4* xg = reinterpret_cast<const float4*>(x + (size_t)s * 24);
#pragma unroll
        for (int i = 0; i < 6; i++) {
            float4 v = xg[i];
            xv[4*i] = v.x; xv[4*i+1] = v.y; xv[4*i+2] = v.z; xv[4*i+3] = v.w;
        }
    }

    // ============ stage A: conv11 -> relu -> conv12 -> relu -> pool -> p1 (smem) ============
    float h1[4][8];
    auto H1 = [&](int pos) {
        float xm = (pos > 0)  ? xv[pos - 1] : 0.f;
        float xc = xv[pos];
        float xp = (pos < 23) ? xv[pos + 1] : 0.f;
        float* d = h1[pos & 3];
#pragma unroll
        for (int c = 0; c < 8; c++)
            d[c] = fmaxf(fmaf(c_pack[3648 + 16 + c], xp,
                         fmaf(c_pack[3648 + 8 + c],  xc,
                         fmaf(c_pack[3648 + c],      xm, c_pack[3672 + c]))), 0.f);
    };
    H1(0); H1(1); H1(2);

#pragma unroll
    for (int t = 0; t < 12; t++) {
        u64 Ae[4], Ao[4];
        {
            uu2 b01 = cpk4(3680), b23 = cpk4(3684);
            Ae[0] = b01.a; Ae[1] = b01.b; Ae[2] = b23.a; Ae[3] = b23.b;
            Ao[0] = b01.a; Ao[1] = b01.b; Ao[2] = b23.a; Ao[3] = b23.b;
        }
#pragma unroll
        for (int ci = 0; ci < 8; ci++) {
#pragma unroll
            for (int k = 0; k < 3; k++) {
                int pe = 2*t + k - 1, po = 2*t + k;
                u64 se = (pe < 0)  ? 0ull : pk2(h1[pe & 3][ci], h1[pe & 3][ci]);
                u64 so = (po > 23) ? 0ull : pk2(h1[po & 3][ci], h1[po & 3][ci]);
                uu2 w01 = cpk4((ci*3 + k) * 8);
                uu2 w23 = cpk4((ci*3 + k) * 8 + 4);
                Ae[0] = ffma2(w01.a, se, Ae[0]);  Ao[0] = ffma2(w01.a, so, Ao[0]);
                Ae[1] = ffma2(w01.b, se, Ae[1]);  Ao[1] = ffma2(w01.b, so, Ao[1]);
                Ae[2] = ffma2(w23.a, se, Ae[2]);  Ao[2] = ffma2(w23.a, so, Ao[2]);
                Ae[3] = ffma2(w23.b, se, Ae[3]);  Ao[3] = ffma2(w23.b, so, Ao[3]);
            }
        }
#pragma unroll
        for (int p = 0; p < 4; p++) {
            float2 e = upk2(Ae[p]), o = upk2(Ao[p]);
            p1s[((2*p)     * 12 + t) * P1_STRIDE] = fmaxf(fmaxf(e.x, o.x), 0.f);
            p1s[((2*p + 1) * 12 + t) * P1_STRIDE] = fmaxf(fmaxf(e.y, o.y), 0.f);
        }
        if (t < 11) H1(2*t + 3);
        if (t < 10) H1(2*t + 4);
    }

    // ============ stage B: conv21 -> relu -> conv22 -> relu -> pool -> p2 (global) ============
    float r3[3][16];
    auto H3 = [&](int j) {
        u64 D[8];
#pragma unroll
        for (int h = 0; h < 4; h++) {
            uu2 b = cpk4(3688 + 4*h);
            D[2*h] = b.a; D[2*h + 1] = b.b;
        }
#pragma unroll
        for (int ci = 0; ci < 8; ci++) {
#pragma unroll
            for (int k = 0; k < 3; k++) {
                int col = j + k - 1;
                if (col >= 0 && col <= 11) {
                    float g = p1s[(ci * 12 + col) * P1_STRIDE];
                    u64 sg = pk2(g, g);
                    int wb = 192 + (ci*3 + k) * 16;
#pragma unroll
                    for (int h = 0; h < 4; h++) {
                        uu2 w = cpk4(wb + 4*h);
                        D[2*h]     = ffma2(w.a, sg, D[2*h]);
                        D[2*h + 1] = ffma2(w.b, sg, D[2*h + 1]);
                    }
                }
            }
        }
        float* o = r3[j % 3];
#pragma unroll
        for (int p = 0; p < 8; p++) {
            float2 v = upk2(D[p]);
            o[2*p] = fmaxf(v.x, 0.f); o[2*p + 1] = fmaxf(v.y, 0.f);
        }
    };

    auto C22 = [&](int pos, u64 A[8]) {
#pragma unroll
        for (int h = 0; h < 4; h++) {
            uu2 b = cpk4(3704 + 4*h);
            A[2*h] = b.a; A[2*h + 1] = b.b;
        }
#pragma unroll
        for (int ci = 0; ci < 16; ci++) {
#pragma unroll
            for (int k = 0; k < 3; k++) {
                int col = pos + k - 1;
                if (col >= 0 && col <= 11) {
                    float g = r3[col % 3][ci];
                    u64 sg = pk2(g, g);
                    int wb = 576 + (ci*3 + k) * 16;
#pragma unroll
                    for (int h = 0; h < 4; h++) {
                        uu2 w = cpk4(wb + 4*h);
                        A[2*h]     = ffma2(w.a, sg, A[2*h]);
                        A[2*h + 1] = ffma2(w.b, sg, A[2*h + 1]);
                    }
                }
            }
        }
    };

    H3(0); H3(1);
#pragma unroll
    for (int t2 = 0; t2 < 6; t2++) {
        u64 AA[8], AB[8];
        C22(2*t2, AA);
        if (2*t2 + 2 <= 11) H3(2*t2 + 2);
        C22(2*t2 + 1, AB);
#pragma unroll
        for (int p = 0; p < 8; p++) {
            float2 a = upk2(AA[p]), b = upk2(AB[p]);
            g_p2[(size_t)(t2 * 16 + 2*p)     * n + s] = fmaxf(fmaxf(a.x, b.x), 0.f);
            g_p2[(size_t)(t2 * 16 + 2*p + 1) * n + s] = fmaxf(fmaxf(a.y, b.y), 0.f);
        }
        if (2*t2 + 3 <= 11) H3(2*t2 + 3);
    }
}

// half-grid, straight-line: each thread handles sample s, then s+half (single wave on chip)
__global__ void __launch_bounds__(128, 4)
cnn_main(const float* __restrict__ x, int n, int half)
{
    extern __shared__ float p1s_base[];
    float* p1s = p1s_base + threadIdx.x;

    int s = blockIdx.x * 128 + threadIdx.x;
    if (s >= half) return;
    process_sample(x, p1s, s, n);
    int s2 = s + half;
    if (s2 < n) process_sample(x, p1s, s2, n);
}

// ============ linear: out = p2 @ Wl^T + bl ; 2 samples/thread sharing weight fetches =========
__global__ void __launch_bounds__(128)
lin_kernel(float* __restrict__ out, int n, int half)
{
    int s = blockIdx.x * 128 + threadIdx.x;
    if (s >= half) return;
    int sB = s + half;
    bool hasB = (sB < n);

    u64 accA[12], accB[12];
#pragma unroll
    for (int h = 0; h < 6; h++) {
        uu2 b = cpk4(3720 + 4*h);
        accA[2*h] = b.a; accA[2*h + 1] = b.b;
        accB[2*h] = b.a; accB[2*h + 1] = b.b;
    }
#pragma unroll 8
    for (int r = 0; r < 96; r++) {
        float vA = g_p2[(size_t)r * n + s];
        float vB = hasB ? g_p2[(size_t)r * n + sB] : 0.f;
        u64 sA = pk2(vA, vA), sB2 = pk2(vB, vB);
        int wb = 1344 + r * 24;
#pragma unroll
        for (int h = 0; h < 6; h++) {
            uu2 w = cpk4(wb + 4*h);
            accA[2*h]     = ffma2(w.a, sA, accA[2*h]);
            accA[2*h + 1] = ffma2(w.b, sA, accA[2*h + 1]);
            accB[2*h]     = ffma2(w.a, sB2, accB[2*h]);
            accB[2*h + 1] = ffma2(w.b, sB2, accB[2*h + 1]);
        }
    }

    {
        float res[24];
#pragma unroll
        for (int q = 0; q < 12; q++) {
            float2 v = upk2(accA[q]);
            res[2*q] = v.x; res[2*q + 1] = v.y;
        }
        float4* og = reinterpret_cast<float4*>(out + (size_t)s * 24);
#pragma unroll
        for (int i = 0; i < 6; i++)
            og[i] = make_float4(res[4*i], res[4*i+1], res[4*i+2], res[4*i+3]);
    }
    if (hasB) {
        float res[24];
#pragma unroll
        for (int q = 0; q < 12; q++) {
            float2 v = upk2(accB[q]);
            res[2*q] = v.x; res[2*q + 1] = v.y;
        }
        float4* og = reinterpret_cast<float4*>(out + (size_t)sB * 24);
#pragma unroll
        for (int i = 0; i < 6; i++)
            og[i] = make_float4(res[4*i], res[4*i+1], res[4*i+2], res[4*i+3]);
    }
}

extern "C" void kernel_launch(void* const* d_in, const int* in_sizes, int n_in,
                              void* d_out, int out_size)
{
    const float* x = (const float*)d_in[0];

    repack_kernel<<<10, 256>>>(
        (const float*)d_in[1], (const float*)d_in[2],
        (const float*)d_in[3], (const float*)d_in[4],
        (const float*)d_in[5], (const float*)d_in[6],
        (const float*)d_in[7], (const float*)d_in[8],
        (const float*)d_in[9], (const float*)d_in[10]);

    void *cp, *gp;
    cudaGetSymbolAddress(&cp, c_pack);
    cudaGetSymbolAddress(&gp, g_pack);
    cudaMemcpyAsync(cp, gp, PACKN * sizeof(float), cudaMemcpyDeviceToDevice, 0);

    static bool attr_set = false;
    if (!attr_set) {
        cudaFuncSetAttribute(cnn_main,
                             cudaFuncAttributeMaxDynamicSharedMemorySize, SMEM_BYTES);
        attr_set = true;
    }

    int nSamples = in_sizes[0] / 24;            // 512*256 = 131072 (<= MAXN)
    int half = (nSamples + 1) / 2;
    int blocks = (half + 127) / 128;            // 512 blocks -> single wave at 4 CTAs/SM
    cnn_main<<<blocks, 128, SMEM_BYTES>>>(x, nSamples, half);
    lin_kernel<<<blocks, 128>>>((float*)d_out, nSamples, half);
}

// round 12
// speedup vs baseline: 1.2725x; 1.2725x over previous
#include <cuda_runtime.h>

typedef unsigned long long u64;
struct uu2 { u64 a, b; };

// ---------------- merged constant blob ----------------
// linsp: [r*24+o] = (Wl[o][f(r)], same) splatted, r = t2*16+ch, f = ch*6+t2 ; then 24 splatted bl
// pack:  [0..192) w12p[(ci*3+k)*8+co] | [192..576) w21p[(ci*3+k)*16+co]
//        [576..1344) w22p[(ci*3+k)*16+co] | [1344..3648) unused
//        [3648..3672) w11p[k*8+co] | [3672..3680) b11 | [3680..3688) b12
//        [3688..3704) b21 | [3704..3720) b22 | [3720..3744) bl
#define LINW (96 * 24)
#define PACKN 3744
struct __align__(16) Blob {
    u64   linsp[LINW + 24];
    float pack[PACKN];
};
__device__ Blob g_blob;
__constant__ Blob c_blob;

// p2 scratch [feature r][sample]
#define MAXN 131072
__device__ float g_p2[96 * MAXN];

__device__ __forceinline__ u64 pk2(float lo, float hi) {
    u64 r; asm("mov.b64 %0,{%1,%2};" : "=l"(r) : "f"(lo), "f"(hi)); return r;
}
__device__ __forceinline__ float2 upk2(u64 v) {
    float2 f; asm("mov.b64 {%0,%1},%2;" : "=f"(f.x), "=f"(f.y) : "l"(v)); return f;
}
__device__ __forceinline__ u64 ffma2(u64 a, u64 b, u64 c) {
    u64 d; asm("fma.rn.f32x2 %0,%1,%2,%3;" : "=l"(d) : "l"(a), "l"(b), "l"(c)); return d;
}
__device__ __forceinline__ uu2 cpk4(int idx) {          // LDC.128 from pack (idx mult of 4)
    ulonglong2 v = *reinterpret_cast<const ulonglong2*>(&c_blob.pack[idx]);
    uu2 r; r.a = v.x; r.b = v.y; return r;
}

__global__ void repack_kernel(
    const float* __restrict__ w11, const float* __restrict__ b11,
    const float* __restrict__ w12, const float* __restrict__ b12,
    const float* __restrict__ w21, const float* __restrict__ b21,
    const float* __restrict__ w22, const float* __restrict__ b22,
    const float* __restrict__ Wl,  const float* __restrict__ bl)
{
    int gtid = blockIdx.x * 256 + threadIdx.x;
    int stride = gridDim.x * 256;
    for (int i = gtid; i < 192;  i += stride) g_blob.pack[i]       = w12[(i & 7)  * 24 + (i >> 3)];
    for (int i = gtid; i < 384;  i += stride) g_blob.pack[192 + i] = w21[(i & 15) * 24 + (i >> 4)];
    for (int i = gtid; i < 768;  i += stride) g_blob.pack[576 + i] = w22[(i & 15) * 48 + (i >> 4)];
    for (int i = gtid; i < 2304; i += stride) {
        int o = i % 24; int r = i / 24;
        float w = Wl[o * 96 + (r & 15) * 6 + (r >> 4)];
        g_blob.linsp[i] = pk2(w, w);
    }
    if (gtid < 24) g_blob.linsp[LINW + gtid] = pk2(bl[gtid], bl[gtid]);
    if (gtid < 24) g_blob.pack[3648 + gtid] = w11[(gtid & 7) * 3 + (gtid >> 3)];
    if (gtid < 8)  g_blob.pack[3672 + gtid] = b11[gtid];
    if (gtid < 8)  g_blob.pack[3680 + gtid] = b12[gtid];
    if (gtid < 16) g_blob.pack[3688 + gtid] = b21[gtid];
    if (gtid < 16) g_blob.pack[3704 + gtid] = b22[gtid];
    if (gtid < 24) g_blob.pack[3720 + gtid] = bl[gtid];
}

#define P1_STRIDE 128
#define SMEM_BYTES (96 * 128 * 4)

// ================= main: conv11..pool2 (identical structure to the 160us winner) =========
__global__ void __launch_bounds__(128, 4)
cnn_main(const float* __restrict__ x, int n)
{
    extern __shared__ float p1s_base[];
    float* p1s = p1s_base + threadIdx.x;

    int s = blockIdx.x * 128 + threadIdx.x;
    if (s >= n) return;

    // ---- input sample ----
    float xv[24];
    {
        const float4* xg = reinterpret_cast<const float4*>(x + (size_t)s * 24);
#pragma unroll
        for (int i = 0; i < 6; i++) {
            float4 v = xg[i];
            xv[4*i] = v.x; xv[4*i+1] = v.y; xv[4*i+2] = v.z; xv[4*i+3] = v.w;
        }
    }

    // ============ stage A: conv11 -> relu -> conv12 -> relu -> pool -> p1 (smem) ============
    float h1[4][8];
    auto H1 = [&](int pos) {
        float xm = (pos > 0)  ? xv[pos - 1] : 0.f;
        float xc = xv[pos];
        float xp = (pos < 23) ? xv[pos + 1] : 0.f;
        float* d = h1[pos & 3];
#pragma unroll
        for (int c = 0; c < 8; c++)
            d[c] = fmaxf(fmaf(c_blob.pack[3648 + 16 + c], xp,
                         fmaf(c_blob.pack[3648 + 8 + c],  xc,
                         fmaf(c_blob.pack[3648 + c],      xm, c_blob.pack[3672 + c]))), 0.f);
    };
    H1(0); H1(1); H1(2);

#pragma unroll
    for (int t = 0; t < 12; t++) {
        u64 Ae[4], Ao[4];
        {
            uu2 b01 = cpk4(3680), b23 = cpk4(3684);
            Ae[0] = b01.a; Ae[1] = b01.b; Ae[2] = b23.a; Ae[3] = b23.b;
            Ao[0] = b01.a; Ao[1] = b01.b; Ao[2] = b23.a; Ao[3] = b23.b;
        }
#pragma unroll
        for (int ci = 0; ci < 8; ci++) {
#pragma unroll
            for (int k = 0; k < 3; k++) {
                int pe = 2*t + k - 1, po = 2*t + k;
                u64 se = (pe < 0)  ? 0ull : pk2(h1[pe & 3][ci], h1[pe & 3][ci]);
                u64 so = (po > 23) ? 0ull : pk2(h1[po & 3][ci], h1[po & 3][ci]);
                uu2 w01 = cpk4((ci*3 + k) * 8);
                uu2 w23 = cpk4((ci*3 + k) * 8 + 4);
                Ae[0] = ffma2(w01.a, se, Ae[0]);  Ao[0] = ffma2(w01.a, so, Ao[0]);
                Ae[1] = ffma2(w01.b, se, Ae[1]);  Ao[1] = ffma2(w01.b, so, Ao[1]);
                Ae[2] = ffma2(w23.a, se, Ae[2]);  Ao[2] = ffma2(w23.a, so, Ao[2]);
                Ae[3] = ffma2(w23.b, se, Ae[3]);  Ao[3] = ffma2(w23.b, so, Ao[3]);
            }
        }
#pragma unroll
        for (int p = 0; p < 4; p++) {
            float2 e = upk2(Ae[p]), o = upk2(Ao[p]);
            p1s[((2*p)     * 12 + t) * P1_STRIDE] = fmaxf(fmaxf(e.x, o.x), 0.f);
            p1s[((2*p + 1) * 12 + t) * P1_STRIDE] = fmaxf(fmaxf(e.y, o.y), 0.f);
        }
        if (t < 11) H1(2*t + 3);
        if (t < 10) H1(2*t + 4);
    }

    // ============ stage B: conv21 -> relu -> conv22 -> relu -> pool -> p2 (global) ============
    float r3[3][16];
    auto H3 = [&](int j) {
        u64 D[8];
#pragma unroll
        for (int h = 0; h < 4; h++) {
            uu2 b = cpk4(3688 + 4*h);
            D[2*h] = b.a; D[2*h + 1] = b.b;
        }
#pragma unroll
        for (int ci = 0; ci < 8; ci++) {
#pragma unroll
            for (int k = 0; k < 3; k++) {
                int col = j + k - 1;
                if (col >= 0 && col <= 11) {
                    float g = p1s[(ci * 12 + col) * P1_STRIDE];
                    u64 sg = pk2(g, g);
                    int wb = 192 + (ci*3 + k) * 16;
#pragma unroll
                    for (int h = 0; h < 4; h++) {
                        uu2 w = cpk4(wb + 4*h);
                        D[2*h]     = ffma2(w.a, sg, D[2*h]);
                        D[2*h + 1] = ffma2(w.b, sg, D[2*h + 1]);
                    }
                }
            }
        }
        float* o = r3[j % 3];
#pragma unroll
        for (int p = 0; p < 8; p++) {
            float2 v = upk2(D[p]);
            o[2*p] = fmaxf(v.x, 0.f); o[2*p + 1] = fmaxf(v.y, 0.f);
        }
    };

    auto C22 = [&](int pos, u64 A[8]) {
#pragma unroll
        for (int h = 0; h < 4; h++) {
            uu2 b = cpk4(3704 + 4*h);
            A[2*h] = b.a; A[2*h + 1] = b.b;
        }
#pragma unroll
        for (int ci = 0; ci < 16; ci++) {
#pragma unroll
            for (int k = 0; k < 3; k++) {
                int col = pos + k - 1;
                if (col >= 0 && col <= 11) {
                    float g = r3[col % 3][ci];
                    u64 sg = pk2(g, g);
                    int wb = 576 + (ci*3 + k) * 16;
#pragma unroll
                    for (int h = 0; h < 4; h++) {
                        uu2 w = cpk4(wb + 4*h);
                        A[2*h]     = ffma2(w.a, sg, A[2*h]);
                        A[2*h + 1] = ffma2(w.b, sg, A[2*h + 1]);
                    }
                }
            }
        }
    };

    H3(0); H3(1);
#pragma unroll
    for (int t2 = 0; t2 < 6; t2++) {
        u64 AA[8], AB[8];
        C22(2*t2, AA);
        if (2*t2 + 2 <= 11) H3(2*t2 + 2);
        C22(2*t2 + 1, AB);
#pragma unroll
        for (int p = 0; p < 8; p++) {
            float2 a = upk2(AA[p]), b = upk2(AB[p]);
            g_p2[(size_t)(t2 * 16 + 2*p)     * n + s] = fmaxf(fmaxf(a.x, b.x), 0.f);
            g_p2[(size_t)(t2 * 16 + 2*p + 1) * n + s] = fmaxf(fmaxf(a.y, b.y), 0.f);
        }
        if (2*t2 + 3 <= 11) H3(2*t2 + 3);
    }
}

// ============ linear: 2 adjacent samples per thread, samples in f32x2 lanes ==========
// acc[o] = (out_{s0}[o], out_{s0+1}[o]); weights pre-splatted -> zero runtime splats.
__global__ void __launch_bounds__(128)
lin_kernel(float* __restrict__ out, int n)
{
    int i = blockIdx.x * 128 + threadIdx.x;
    int s0 = 2 * i;
    if (s0 >= n) return;
    bool hasB = (s0 + 1 < n);

    u64 acc[24];
#pragma unroll
    for (int o = 0; o < 24; o++) acc[o] = c_blob.linsp[LINW + o];

    if (hasB) {
#pragma unroll 8
        for (int r = 0; r < 96; r++) {
            float2 v = *reinterpret_cast<const float2*>(&g_p2[(size_t)r * n + s0]);
            u64 pv = pk2(v.x, v.y);
            const u64* w = &c_blob.linsp[r * 24];
#pragma unroll
            for (int h = 0; h < 12; h++) {
                ulonglong2 w2 = *reinterpret_cast<const ulonglong2*>(&w[2*h]);
                acc[2*h]     = ffma2(w2.x, pv, acc[2*h]);
                acc[2*h + 1] = ffma2(w2.y, pv, acc[2*h + 1]);
            }
        }
        float rA[24], rB[24];
#pragma unroll
        for (int o = 0; o < 24; o++) {
            float2 v = upk2(acc[o]);
            rA[o] = v.x; rB[o] = v.y;
        }
        float4* oA = reinterpret_cast<float4*>(out + (size_t)s0 * 24);
        float4* oB = reinterpret_cast<float4*>(out + (size_t)(s0 + 1) * 24);
#pragma unroll
        for (int q = 0; q < 6; q++) {
            oA[q] = make_float4(rA[4*q], rA[4*q+1], rA[4*q+2], rA[4*q+3]);
            oB[q] = make_float4(rB[4*q], rB[4*q+1], rB[4*q+2], rB[4*q+3]);
        }
    } else {
        // odd tail: single sample in lane 0
#pragma unroll 8
        for (int r = 0; r < 96; r++) {
            float v = g_p2[(size_t)r * n + s0];
            u64 pv = pk2(v, 0.f);
            const u64* w = &c_blob.linsp[r * 24];
#pragma unroll
            for (int h = 0; h < 12; h++) {
                ulonglong2 w2 = *reinterpret_cast<const ulonglong2*>(&w[2*h]);
                acc[2*h]     = ffma2(w2.x, pv, acc[2*h]);
                acc[2*h + 1] = ffma2(w2.y, pv, acc[2*h + 1]);
            }
        }
        float rA[24];
#pragma unroll
        for (int o = 0; o < 24; o++) rA[o] = upk2(acc[o]).x;
        float4* oA = reinterpret_cast<float4*>(out + (size_t)s0 * 24);
#pragma unroll
        for (int q = 0; q < 6; q++)
            oA[q] = make_float4(rA[4*q], rA[4*q+1], rA[4*q+2], rA[4*q+3]);
    }
}

extern "C" void kernel_launch(void* const* d_in, const int* in_sizes, int n_in,
                              void* d_out, int out_size)
{
    const float* x = (const float*)d_in[0];

    repack_kernel<<<10, 256>>>(
        (const float*)d_in[1], (const float*)d_in[2],
        (const float*)d_in[3], (const float*)d_in[4],
        (const float*)d_in[5], (const float*)d_in[6],
        (const float*)d_in[7], (const float*)d_in[8],
        (const float*)d_in[9], (const float*)d_in[10]);

    void *cb, *gb;
    cudaGetSymbolAddress(&cb, c_blob);
    cudaGetSymbolAddress(&gb, g_blob);
    cudaMemcpyAsync(cb, gb, sizeof(Blob), cudaMemcpyDeviceToDevice, 0);

    static bool attr_set = false;
    if (!attr_set) {
        cudaFuncSetAttribute(cnn_main,
                             cudaFuncAttributeMaxDynamicSharedMemorySize, SMEM_BYTES);
        attr_set = true;
    }

    int nSamples = in_sizes[0] / 24;            // 512*256 = 131072 (<= MAXN)
    int blocks = (nSamples + 127) / 128;
    cnn_main<<<blocks, 128, SMEM_BYTES>>>(x, nSamples);

    int lblocks = ((nSamples + 1) / 2 + 127) / 128;
    lin_kernel<<<lblocks, 128>>>((float*)d_out, nSamples);
}

// round 13
// speedup vs baseline: 1.2819x; 1.0074x over previous
#include <cuda_runtime.h>

typedef unsigned long long u64;
struct uu2 { u64 a, b; };

// ---------------- merged constant blob ----------------
// linsp: [r*24+o] = (Wl[o][f(r)], same) splatted, r = t2*16+ch, f = ch*6+t2 ; then 24 splatted bl
// pack:  [0..192) w12p[(ci*3+k)*8+co] | [192..576) w21p[(ci*3+k)*16+co]
//        [576..1344) w22p[(ci*3+k)*16+co]
//        [3648..3672) w11p[k*8+co] | [3672..3680) b11 | [3680..3688) b12
//        [3688..3704) b21 | [3704..3720) b22 | [3720..3744) bl
#define LINW (96 * 24)
#define PACKN 3744
struct __align__(16) Blob {
    u64   linsp[LINW + 24];
    float pack[PACKN];
};
__device__ Blob g_blob;
__constant__ Blob c_blob;

// p2 scratch [feature r][sample]
#define MAXN 131072
__device__ float g_p2[96 * MAXN];

__device__ __forceinline__ u64 pk2(float lo, float hi) {
    u64 r; asm("mov.b64 %0,{%1,%2};" : "=l"(r) : "f"(lo), "f"(hi)); return r;
}
__device__ __forceinline__ float2 upk2(u64 v) {
    float2 f; asm("mov.b64 {%0,%1},%2;" : "=f"(f.x), "=f"(f.y) : "l"(v)); return f;
}
__device__ __forceinline__ u64 ffma2(u64 a, u64 b, u64 c) {
    u64 d; asm("fma.rn.f32x2 %0,%1,%2,%3;" : "=l"(d) : "l"(a), "l"(b), "l"(c)); return d;
}
__device__ __forceinline__ uu2 cpk4(int idx) {          // LDC.128 from pack (idx mult of 4)
    ulonglong2 v = *reinterpret_cast<const ulonglong2*>(&c_blob.pack[idx]);
    uu2 r; r.a = v.x; r.b = v.y; return r;
}

__global__ void repack_kernel(
    const float* __restrict__ w11, const float* __restrict__ b11,
    const float* __restrict__ w12, const float* __restrict__ b12,
    const float* __restrict__ w21, const float* __restrict__ b21,
    const float* __restrict__ w22, const float* __restrict__ b22,
    const float* __restrict__ Wl,  const float* __restrict__ bl)
{
    int gtid = blockIdx.x * 256 + threadIdx.x;
    int stride = gridDim.x * 256;
    for (int i = gtid; i < 192;  i += stride) g_blob.pack[i]       = w12[(i & 7)  * 24 + (i >> 3)];
    for (int i = gtid; i < 384;  i += stride) g_blob.pack[192 + i] = w21[(i & 15) * 24 + (i >> 4)];
    for (int i = gtid; i < 768;  i += stride) g_blob.pack[576 + i] = w22[(i & 15) * 48 + (i >> 4)];
    for (int i = gtid; i < 2304; i += stride) {
        int o = i % 24; int r = i / 24;
        float w = Wl[o * 96 + (r & 15) * 6 + (r >> 4)];
        g_blob.linsp[i] = pk2(w, w);
    }
    if (gtid < 24) g_blob.linsp[LINW + gtid] = pk2(bl[gtid], bl[gtid]);
    if (gtid < 24) g_blob.pack[3648 + gtid] = w11[(gtid & 7) * 3 + (gtid >> 3)];
    if (gtid < 8)  g_blob.pack[3672 + gtid] = b11[gtid];
    if (gtid < 8)  g_blob.pack[3680 + gtid] = b12[gtid];
    if (gtid < 16) g_blob.pack[3688 + gtid] = b21[gtid];
    if (gtid < 16) g_blob.pack[3704 + gtid] = b22[gtid];
    if (gtid < 24) g_blob.pack[3720 + gtid] = bl[gtid];
}

#define P1_STRIDE 128
#define SMEM_BYTES (96 * 128 * 4)

// ================= main: conv11..pool2 =================
__global__ void __launch_bounds__(128, 4)
cnn_main(const float* __restrict__ x, int n)
{
    extern __shared__ float p1s_base[];
    float* p1s = p1s_base + threadIdx.x;

    int s = blockIdx.x * 128 + threadIdx.x;
    if (s >= n) return;

    // ---- input sample ----
    float xv[24];
    {
        const float4* xg = reinterpret_cast<const float4*>(x + (size_t)s * 24);
#pragma unroll
        for (int i = 0; i < 6; i++) {
            float4 v = xg[i];
            xv[4*i] = v.x; xv[4*i+1] = v.y; xv[4*i+2] = v.z; xv[4*i+3] = v.w;
        }
    }

    // ============ stage A: conv11 -> relu -> conv12 -> relu -> pool -> p1 (smem) ============
    // h1 ring holds channel-pair packed (c,c+1) values
    u64 h1[4][4];
    auto H1 = [&](int pos) {
        float xm = (pos > 0)  ? xv[pos - 1] : 0.f;
        float xc = xv[pos];
        float xp = (pos < 23) ? xv[pos + 1] : 0.f;
        u64 sm_ = pk2(xm, xm), sc = pk2(xc, xc), sp = pk2(xp, xp);
        u64* d = h1[pos & 3];
        uu2 b01 = cpk4(3672), b23 = cpk4(3676);          // b11 pairs
        u64 acc[4] = {b01.a, b01.b, b23.a, b23.b};
        uu2 wk0 = cpk4(3648),      wk0b = cpk4(3652);    // k=0 pairs
        uu2 wk1 = cpk4(3648 + 8),  wk1b = cpk4(3648 + 12);
        uu2 wk2 = cpk4(3648 + 16), wk2b = cpk4(3648 + 20);
        acc[0] = ffma2(wk0.a,  sm_, acc[0]); acc[1] = ffma2(wk0.b,  sm_, acc[1]);
        acc[2] = ffma2(wk0b.a, sm_, acc[2]); acc[3] = ffma2(wk0b.b, sm_, acc[3]);
        acc[0] = ffma2(wk1.a,  sc,  acc[0]); acc[1] = ffma2(wk1.b,  sc,  acc[1]);
        acc[2] = ffma2(wk1b.a, sc,  acc[2]); acc[3] = ffma2(wk1b.b, sc,  acc[3]);
        acc[0] = ffma2(wk2.a,  sp,  acc[0]); acc[1] = ffma2(wk2.b,  sp,  acc[1]);
        acc[2] = ffma2(wk2b.a, sp,  acc[2]); acc[3] = ffma2(wk2b.b, sp,  acc[3]);
#pragma unroll
        for (int p = 0; p < 4; p++) {
            float2 v = upk2(acc[p]);
            d[p] = pk2(fmaxf(v.x, 0.f), fmaxf(v.y, 0.f));
        }
    };
    H1(0); H1(1); H1(2);

#pragma unroll
    for (int t = 0; t < 12; t++) {
        u64 Ae[4], Ao[4];
        {
            uu2 b01 = cpk4(3680), b23 = cpk4(3684);
            Ae[0] = b01.a; Ae[1] = b01.b; Ae[2] = b23.a; Ae[3] = b23.b;
            Ao[0] = b01.a; Ao[1] = b01.b; Ao[2] = b23.a; Ao[3] = b23.b;
        }
#pragma unroll
        for (int ci = 0; ci < 8; ci++) {
#pragma unroll
            for (int k = 0; k < 3; k++) {
                int pe = 2*t + k - 1, po = 2*t + k;
                // splat single channel ci out of the packed h1 pair
                float ge = 0.f, go = 0.f;
                if (pe >= 0) {
                    float2 v = upk2(h1[pe & 3][ci >> 1]);
                    ge = (ci & 1) ? v.y : v.x;
                }
                if (po <= 23) {
                    float2 v = upk2(h1[po & 3][ci >> 1]);
                    go = (ci & 1) ? v.y : v.x;
                }
                u64 se = pk2(ge, ge), so = pk2(go, go);
                uu2 w01 = cpk4((ci*3 + k) * 8);
                uu2 w23 = cpk4((ci*3 + k) * 8 + 4);
                Ae[0] = ffma2(w01.a, se, Ae[0]);  Ao[0] = ffma2(w01.a, so, Ao[0]);
                Ae[1] = ffma2(w01.b, se, Ae[1]);  Ao[1] = ffma2(w01.b, so, Ao[1]);
                Ae[2] = ffma2(w23.a, se, Ae[2]);  Ao[2] = ffma2(w23.a, so, Ao[2]);
                Ae[3] = ffma2(w23.b, se, Ae[3]);  Ao[3] = ffma2(w23.b, so, Ao[3]);
            }
        }
#pragma unroll
        for (int p = 0; p < 4; p++) {
            float2 e = upk2(Ae[p]), o = upk2(Ao[p]);
            p1s[((2*p)     * 12 + t) * P1_STRIDE] = fmaxf(fmaxf(e.x, o.x), 0.f);
            p1s[((2*p + 1) * 12 + t) * P1_STRIDE] = fmaxf(fmaxf(e.y, o.y), 0.f);
        }
        if (t < 11) H1(2*t + 3);
        if (t < 10) H1(2*t + 4);
    }

    // ============ stage B: conv21 -> relu -> conv22 -> relu -> pool -> p2 (global) ============
    float r3[3][16];
    auto H3 = [&](int j) {
        u64 D[8];
#pragma unroll
        for (int h = 0; h < 4; h++) {
            uu2 b = cpk4(3688 + 4*h);
            D[2*h] = b.a; D[2*h + 1] = b.b;
        }
#pragma unroll
        for (int ci = 0; ci < 8; ci++) {
#pragma unroll
            for (int k = 0; k < 3; k++) {
                int col = j + k - 1;
                if (col >= 0 && col <= 11) {
                    float g = p1s[(ci * 12 + col) * P1_STRIDE];
                    u64 sg = pk2(g, g);
                    int wb = 192 + (ci*3 + k) * 16;
#pragma unroll
                    for (int h = 0; h < 4; h++) {
                        uu2 w = cpk4(wb + 4*h);
                        D[2*h]     = ffma2(w.a, sg, D[2*h]);
                        D[2*h + 1] = ffma2(w.b, sg, D[2*h + 1]);
                    }
                }
            }
        }
        float* o = r3[j % 3];
#pragma unroll
        for (int p = 0; p < 8; p++) {
            float2 v = upk2(D[p]);
            o[2*p] = fmaxf(v.x, 0.f); o[2*p + 1] = fmaxf(v.y, 0.f);
        }
    };

    auto C22 = [&](int pos, u64 A[8]) {
#pragma unroll
        for (int h = 0; h < 4; h++) {
            uu2 b = cpk4(3704 + 4*h);
            A[2*h] = b.a; A[2*h + 1] = b.b;
        }
#pragma unroll
        for (int ci = 0; ci < 16; ci++) {
#pragma unroll
            for (int k = 0; k < 3; k++) {
                int col = pos + k - 1;
                if (col >= 0 && col <= 11) {
                    float g = r3[col % 3][ci];
                    u64 sg = pk2(g, g);
                    int wb = 576 + (ci*3 + k) * 16;
#pragma unroll
                    for (int h = 0; h < 4; h++) {
                        uu2 w = cpk4(wb + 4*h);
                        A[2*h]     = ffma2(w.a, sg, A[2*h]);
                        A[2*h + 1] = ffma2(w.b, sg, A[2*h + 1]);
                    }
                }
            }
        }
    };

    H3(0); H3(1);
#pragma unroll
    for (int t2 = 0; t2 < 6; t2++) {
        u64 AA[8], AB[8];
        C22(2*t2, AA);
        if (2*t2 + 2 <= 11) H3(2*t2 + 2);
        C22(2*t2 + 1, AB);
#pragma unroll
        for (int p = 0; p < 8; p++) {
            float2 a = upk2(AA[p]), b = upk2(AB[p]);
            g_p2[(size_t)(t2 * 16 + 2*p)     * n + s] = fmaxf(fmaxf(a.x, b.x), 0.f);
            g_p2[(size_t)(t2 * 16 + 2*p + 1) * n + s] = fmaxf(fmaxf(a.y, b.y), 0.f);
        }
        if (2*t2 + 3 <= 11) H3(2*t2 + 3);
    }
}

// ============ linear: 2 adjacent samples per thread, samples in f32x2 lanes ==========
__global__ void __launch_bounds__(128)
lin_kernel(float* __restrict__ out, int n)
{
    int i = blockIdx.x * 128 + threadIdx.x;
    int s0 = 2 * i;
    if (s0 + 1 >= n) {                   // n even in practice; cheap guard for odd tails
        if (s0 < n) {
            float acc[24];
#pragma unroll
            for (int o = 0; o < 24; o++) acc[o] = upk2(c_blob.linsp[LINW + o]).x;
            for (int r = 0; r < 96; r++) {
                float v = g_p2[(size_t)r * n + s0];
#pragma unroll
                for (int o = 0; o < 24; o++)
                    acc[o] = fmaf(upk2(c_blob.linsp[r*24 + o]).x, v, acc[o]);
            }
#pragma unroll
            for (int o = 0; o < 24; o++) out[(size_t)s0 * 24 + o] = acc[o];
        }
        return;
    }

    u64 acc[24];
#pragma unroll
    for (int o = 0; o < 24; o++) acc[o] = c_blob.linsp[LINW + o];

#pragma unroll 8
    for (int r = 0; r < 96; r++) {
        float2 v = *reinterpret_cast<const float2*>(&g_p2[(size_t)r * n + s0]);
        u64 pv = pk2(v.x, v.y);
        const u64* w = &c_blob.linsp[r * 24];
#pragma unroll
        for (int h = 0; h < 12; h++) {
            ulonglong2 w2 = *reinterpret_cast<const ulonglong2*>(&w[2*h]);
            acc[2*h]     = ffma2(w2.x, pv, acc[2*h]);
            acc[2*h + 1] = ffma2(w2.y, pv, acc[2*h + 1]);
        }
    }
    float rA[24], rB[24];
#pragma unroll
    for (int o = 0; o < 24; o++) {
        float2 v = upk2(acc[o]);
        rA[o] = v.x; rB[o] = v.y;
    }
    float4* oA = reinterpret_cast<float4*>(out + (size_t)s0 * 24);
    float4* oB = reinterpret_cast<float4*>(out + (size_t)(s0 + 1) * 24);
#pragma unroll
    for (int q = 0; q < 6; q++) {
        oA[q] = make_float4(rA[4*q], rA[4*q+1], rA[4*q+2], rA[4*q+3]);
        oB[q] = make_float4(rB[4*q], rB[4*q+1], rB[4*q+2], rB[4*q+3]);
    }
}

extern "C" void kernel_launch(void* const* d_in, const int* in_sizes, int n_in,
                              void* d_out, int out_size)
{
    const float* x = (const float*)d_in[0];

    repack_kernel<<<10, 256>>>(
        (const float*)d_in[1], (const float*)d_in[2],
        (const float*)d_in[3], (const float*)d_in[4],
        (const float*)d_in[5], (const float*)d_in[6],
        (const float*)d_in[7], (const float*)d_in[8],
        (const float*)d_in[9], (const float*)d_in[10]);

    void *cb, *gb;
    cudaGetSymbolAddress(&cb, c_blob);
    cudaGetSymbolAddress(&gb, g_blob);
    cudaMemcpyAsync(cb, gb, sizeof(Blob), cudaMemcpyDeviceToDevice, 0);

    static bool attr_set = false;
    if (!attr_set) {
        cudaFuncSetAttribute(cnn_main,
                             cudaFuncAttributeMaxDynamicSharedMemorySize, SMEM_BYTES);
        attr_set = true;
    }

    int nSamples = in_sizes[0] / 24;            // 512*256 = 131072 (<= MAXN)
    int blocks = (nSamples + 127) / 128;
    cnn_main<<<blocks, 128, SMEM_BYTES>>>(x, nSamples);

    int lblocks = ((nSamples + 1) / 2 + 127) / 128;
    lin_kernel<<<lblocks, 128>>>((float*)d_out, nSamples);
}

// round 14
// speedup vs baseline: 1.3356x; 1.0418x over previous
#include <cuda_runtime.h>

typedef unsigned long long u64;
struct uu2 { u64 a, b; };

// ---------------- merged constant blob ----------------
// linsp: [r*24+o] = (Wl[o][f(r)], same) splatted, r = t2*16+ch, f = ch*6+t2 ; then 24 splatted bl
// pack:  [0..192) w12p[(ci*3+k)*8+co] | [192..576) w21p[(ci*3+k)*16+co]
//        [576..1344) w22p[(ci*3+k)*16+co]
//        [3648..3672) w11p[k*8+co] | [3672..3680) b11 | [3680..3688) b12
//        [3688..3704) b21 | [3704..3720) b22 | [3720..3744) bl
#define LINW (96 * 24)
#define PACKN 3744
struct __align__(16) Blob {
    u64   linsp[LINW + 24];
    float pack[PACKN];
};
__device__ Blob g_blob;
__constant__ Blob c_blob;

// p2 scratch [feature r][sample]
#define MAXN 131072
__device__ float g_p2[96 * MAXN];

__device__ __forceinline__ u64 pk2(float lo, float hi) {
    u64 r; asm("mov.b64 %0,{%1,%2};" : "=l"(r) : "f"(lo), "f"(hi)); return r;
}
__device__ __forceinline__ float2 upk2(u64 v) {
    float2 f; asm("mov.b64 {%0,%1},%2;" : "=f"(f.x), "=f"(f.y) : "l"(v)); return f;
}
__device__ __forceinline__ u64 ffma2(u64 a, u64 b, u64 c) {
    u64 d; asm("fma.rn.f32x2 %0,%1,%2,%3;" : "=l"(d) : "l"(a), "l"(b), "l"(c)); return d;
}
__device__ __forceinline__ uu2 cpk4(int idx) {          // LDC.128 from pack (idx mult of 4)
    ulonglong2 v = *reinterpret_cast<const ulonglong2*>(&c_blob.pack[idx]);
    uu2 r; r.a = v.x; r.b = v.y; return r;
}

__global__ void repack_kernel(
    const float* __restrict__ w11, const float* __restrict__ b11,
    const float* __restrict__ w12, const float* __restrict__ b12,
    const float* __restrict__ w21, const float* __restrict__ b21,
    const float* __restrict__ w22, const float* __restrict__ b22,
    const float* __restrict__ Wl,  const float* __restrict__ bl)
{
    int gtid = blockIdx.x * 256 + threadIdx.x;
    int stride = gridDim.x * 256;
    for (int i = gtid; i < 192;  i += stride) g_blob.pack[i]       = w12[(i & 7)  * 24 + (i >> 3)];
    for (int i = gtid; i < 384;  i += stride) g_blob.pack[192 + i] = w21[(i & 15) * 24 + (i >> 4)];
    for (int i = gtid; i < 768;  i += stride) g_blob.pack[576 + i] = w22[(i & 15) * 48 + (i >> 4)];
    for (int i = gtid; i < 2304; i += stride) {
        int o = i % 24; int r = i / 24;
        float w = Wl[o * 96 + (r & 15) * 6 + (r >> 4)];
        g_blob.linsp[i] = pk2(w, w);
    }
    if (gtid < 24) g_blob.linsp[LINW + gtid] = pk2(bl[gtid], bl[gtid]);
    if (gtid < 24) g_blob.pack[3648 + gtid] = w11[(gtid & 7) * 3 + (gtid >> 3)];
    if (gtid < 8)  g_blob.pack[3672 + gtid] = b11[gtid];
    if (gtid < 8)  g_blob.pack[3680 + gtid] = b12[gtid];
    if (gtid < 16) g_blob.pack[3688 + gtid] = b21[gtid];
    if (gtid < 16) g_blob.pack[3704 + gtid] = b22[gtid];
    if (gtid < 24) g_blob.pack[3720 + gtid] = bl[gtid];
}

#define P1_STRIDE 128
#define SMEM_BYTES (96 * 128 * 4)

// One full sample: conv11 -> relu -> conv12 -> relu -> pool -> conv21 -> relu
//                  -> conv22 -> relu -> pool -> p2 (global).
// __noinline__: single code copy (I$-friendly), called twice straight-line from the
// kernel (no runtime loop -> ptxas keeps arrays in registers).
__device__ __noinline__ void process_sample(const float* __restrict__ x,
                                            float* __restrict__ p1s, int s, int n)
{
    // ---- input sample ----
    float xv[24];
    {
        const float4* xg = reinterpret_cast<const float4*>(x + (size_t)s * 24);
#pragma unroll
        for (int i = 0; i < 6; i++) {
            float4 v = xg[i];
            xv[4*i] = v.x; xv[4*i+1] = v.y; xv[4*i+2] = v.z; xv[4*i+3] = v.w;
        }
    }

    // ============ stage A ============
    u64 h1[4][4];                               // channel-pair packed h1 ring
    auto H1 = [&](int pos) {
        float xm = (pos > 0)  ? xv[pos - 1] : 0.f;
        float xc = xv[pos];
        float xp = (pos < 23) ? xv[pos + 1] : 0.f;
        u64 sm_ = pk2(xm, xm), sc = pk2(xc, xc), sp = pk2(xp, xp);
        u64* d = h1[pos & 3];
        uu2 b01 = cpk4(3672), b23 = cpk4(3676);
        u64 acc[4] = {b01.a, b01.b, b23.a, b23.b};
        uu2 wk0 = cpk4(3648),      wk0b = cpk4(3652);
        uu2 wk1 = cpk4(3648 + 8),  wk1b = cpk4(3648 + 12);
        uu2 wk2 = cpk4(3648 + 16), wk2b = cpk4(3648 + 20);
        acc[0] = ffma2(wk0.a,  sm_, acc[0]); acc[1] = ffma2(wk0.b,  sm_, acc[1]);
        acc[2] = ffma2(wk0b.a, sm_, acc[2]); acc[3] = ffma2(wk0b.b, sm_, acc[3]);
        acc[0] = ffma2(wk1.a,  sc,  acc[0]); acc[1] = ffma2(wk1.b,  sc,  acc[1]);
        acc[2] = ffma2(wk1b.a, sc,  acc[2]); acc[3] = ffma2(wk1b.b, sc,  acc[3]);
        acc[0] = ffma2(wk2.a,  sp,  acc[0]); acc[1] = ffma2(wk2.b,  sp,  acc[1]);
        acc[2] = ffma2(wk2b.a, sp,  acc[2]); acc[3] = ffma2(wk2b.b, sp,  acc[3]);
#pragma unroll
        for (int p = 0; p < 4; p++) {
            float2 v = upk2(acc[p]);
            d[p] = pk2(fmaxf(v.x, 0.f), fmaxf(v.y, 0.f));
        }
    };
    H1(0); H1(1); H1(2);

#pragma unroll
    for (int t = 0; t < 12; t++) {
        u64 Ae[4], Ao[4];
        {
            uu2 b01 = cpk4(3680), b23 = cpk4(3684);
            Ae[0] = b01.a; Ae[1] = b01.b; Ae[2] = b23.a; Ae[3] = b23.b;
            Ao[0] = b01.a; Ao[1] = b01.b; Ao[2] = b23.a; Ao[3] = b23.b;
        }
#pragma unroll
        for (int ci = 0; ci < 8; ci++) {
#pragma unroll
            for (int k = 0; k < 3; k++) {
                int pe = 2*t + k - 1, po = 2*t + k;
                float ge = 0.f, go = 0.f;
                if (pe >= 0) {
                    float2 v = upk2(h1[pe & 3][ci >> 1]);
                    ge = (ci & 1) ? v.y : v.x;
                }
                if (po <= 23) {
                    float2 v = upk2(h1[po & 3][ci >> 1]);
                    go = (ci & 1) ? v.y : v.x;
                }
                u64 se = pk2(ge, ge), so = pk2(go, go);
                uu2 w01 = cpk4((ci*3 + k) * 8);
                uu2 w23 = cpk4((ci*3 + k) * 8 + 4);
                Ae[0] = ffma2(w01.a, se, Ae[0]);  Ao[0] = ffma2(w01.a, so, Ao[0]);
                Ae[1] = ffma2(w01.b, se, Ae[1]);  Ao[1] = ffma2(w01.b, so, Ao[1]);
                Ae[2] = ffma2(w23.a, se, Ae[2]);  Ao[2] = ffma2(w23.a, so, Ao[2]);
                Ae[3] = ffma2(w23.b, se, Ae[3]);  Ao[3] = ffma2(w23.b, so, Ao[3]);
            }
        }
#pragma unroll
        for (int p = 0; p < 4; p++) {
            float2 e = upk2(Ae[p]), o = upk2(Ao[p]);
            p1s[((2*p)     * 12 + t) * P1_STRIDE] = fmaxf(fmaxf(e.x, o.x), 0.f);
            p1s[((2*p + 1) * 12 + t) * P1_STRIDE] = fmaxf(fmaxf(e.y, o.y), 0.f);
        }
        if (t < 11) H1(2*t + 3);
        if (t < 10) H1(2*t + 4);
    }

    // ============ stage B ============
    float r3[3][16];
    auto H3 = [&](int j) {
        u64 D[8];
#pragma unroll
        for (int h = 0; h < 4; h++) {
            uu2 b = cpk4(3688 + 4*h);
            D[2*h] = b.a; D[2*h + 1] = b.b;
        }
#pragma unroll
        for (int ci = 0; ci < 8; ci++) {
#pragma unroll
            for (int k = 0; k < 3; k++) {
                int col = j + k - 1;
                if (col >= 0 && col <= 11) {
                    float g = p1s[(ci * 12 + col) * P1_STRIDE];
                    u64 sg = pk2(g, g);
                    int wb = 192 + (ci*3 + k) * 16;
#pragma unroll
                    for (int h = 0; h < 4; h++) {
                        uu2 w = cpk4(wb + 4*h);
                        D[2*h]     = ffma2(w.a, sg, D[2*h]);
                        D[2*h + 1] = ffma2(w.b, sg, D[2*h + 1]);
                    }
                }
            }
        }
        float* o = r3[j % 3];
#pragma unroll
        for (int p = 0; p < 8; p++) {
            float2 v = upk2(D[p]);
            o[2*p] = fmaxf(v.x, 0.f); o[2*p + 1] = fmaxf(v.y, 0.f);
        }
    };

    auto C22 = [&](int pos, u64 A[8]) {
#pragma unroll
        for (int h = 0; h < 4; h++) {
            uu2 b = cpk4(3704 + 4*h);
            A[2*h] = b.a; A[2*h + 1] = b.b;
        }
#pragma unroll
        for (int ci = 0; ci < 16; ci++) {
#pragma unroll
            for (int k = 0; k < 3; k++) {
                int col = pos + k - 1;
                if (col >= 0 && col <= 11) {
                    float g = r3[col % 3][ci];
                    u64 sg = pk2(g, g);
                    int wb = 576 + (ci*3 + k) * 16;
#pragma unroll
                    for (int h = 0; h < 4; h++) {
                        uu2 w = cpk4(wb + 4*h);
                        A[2*h]     = ffma2(w.a, sg, A[2*h]);
                        A[2*h + 1] = ffma2(w.b, sg, A[2*h + 1]);
                    }
                }
            }
        }
    };

    H3(0); H3(1);
#pragma unroll
    for (int t2 = 0; t2 < 6; t2++) {
        u64 AA[8], AB[8];
        C22(2*t2, AA);
        if (2*t2 + 2 <= 11) H3(2*t2 + 2);
        C22(2*t2 + 1, AB);
#pragma unroll
        for (int p = 0; p < 8; p++) {
            float2 a = upk2(AA[p]), b = upk2(AB[p]);
            g_p2[(size_t)(t2 * 16 + 2*p)     * n + s] = fmaxf(fmaxf(a.x, b.x), 0.f);
            g_p2[(size_t)(t2 * 16 + 2*p + 1) * n + s] = fmaxf(fmaxf(a.y, b.y), 0.f);
        }
        if (2*t2 + 3 <= 11) H3(2*t2 + 3);
    }
}

// half-grid single wave: thread handles sample s, then s+half, via two straight-line
// calls to the (single-copy) __noinline__ body.
__global__ void __launch_bounds__(128, 4)
cnn_main(const float* __restrict__ x, int n, int half)
{
    extern __shared__ float p1s_base[];
    float* p1s = p1s_base + threadIdx.x;

    int s = blockIdx.x * 128 + threadIdx.x;
    if (s >= half) return;
    process_sample(x, p1s, s, n);
    int s2 = s + half;
    if (s2 < n) process_sample(x, p1s, s2, n);
}

// ============ linear: 2 adjacent samples per thread, samples in f32x2 lanes ==========
__global__ void __launch_bounds__(128)
lin_kernel(float* __restrict__ out, int n)
{
    int i = blockIdx.x * 128 + threadIdx.x;
    int s0 = 2 * i;
    if (s0 + 1 >= n) {                   // n even in practice; cheap guard for odd tails
        if (s0 < n) {
            float acc[24];
#pragma unroll
            for (int o = 0; o < 24; o++) acc[o] = upk2(c_blob.linsp[LINW + o]).x;
            for (int r = 0; r < 96; r++) {
                float v = g_p2[(size_t)r * n + s0];
#pragma unroll
                for (int o = 0; o < 24; o++)
                    acc[o] = fmaf(upk2(c_blob.linsp[r*24 + o]).x, v, acc[o]);
            }
#pragma unroll
            for (int o = 0; o < 24; o++) out[(size_t)s0 * 24 + o] = acc[o];
        }
        return;
    }

    u64 acc[24];
#pragma unroll
    for (int o = 0; o < 24; o++) acc[o] = c_blob.linsp[LINW + o];

#pragma unroll 8
    for (int r = 0; r < 96; r++) {
        float2 v = *reinterpret_cast<const float2*>(&g_p2[(size_t)r * n + s0]);
        u64 pv = pk2(v.x, v.y);
        const u64* w = &c_blob.linsp[r * 24];
#pragma unroll
        for (int h = 0; h < 12; h++) {
            ulonglong2 w2 = *reinterpret_cast<const ulonglong2*>(&w[2*h]);
            acc[2*h]     = ffma2(w2.x, pv, acc[2*h]);
            acc[2*h + 1] = ffma2(w2.y, pv, acc[2*h + 1]);
        }
    }
    float rA[24], rB[24];
#pragma unroll
    for (int o = 0; o < 24; o++) {
        float2 v = upk2(acc[o]);
        rA[o] = v.x; rB[o] = v.y;
    }
    float4* oA = reinterpret_cast<float4*>(out + (size_t)s0 * 24);
    float4* oB = reinterpret_cast<float4*>(out + (size_t)(s0 + 1) * 24);
#pragma unroll
    for (int q = 0; q < 6; q++) {
        oA[q] = make_float4(rA[4*q], rA[4*q+1], rA[4*q+2], rA[4*q+3]);
        oB[q] = make_float4(rB[4*q], rB[4*q+1], rB[4*q+2], rB[4*q+3]);
    }
}

extern "C" void kernel_launch(void* const* d_in, const int* in_sizes, int n_in,
                              void* d_out, int out_size)
{
    const float* x = (const float*)d_in[0];

    repack_kernel<<<10, 256>>>(
        (const float*)d_in[1], (const float*)d_in[2],
        (const float*)d_in[3], (const float*)d_in[4],
        (const float*)d_in[5], (const float*)d_in[6],
        (const float*)d_in[7], (const float*)d_in[8],
        (const float*)d_in[9], (const float*)d_in[10]);

    void *cb, *gb;
    cudaGetSymbolAddress(&cb, c_blob);
    cudaGetSymbolAddress(&gb, g_blob);
    cudaMemcpyAsync(cb, gb, sizeof(Blob), cudaMemcpyDeviceToDevice, 0);

    static bool attr_set = false;
    if (!attr_set) {
        cudaFuncSetAttribute(cnn_main,
                             cudaFuncAttributeMaxDynamicSharedMemorySize, SMEM_BYTES);
        attr_set = true;
    }

    int nSamples = in_sizes[0] / 24;            // 512*256 = 131072 (<= MAXN)
    int half = (nSamples + 1) / 2;
    int mblocks = (half + 127) / 128;           // 512 blocks -> single resident wave
    cnn_main<<<mblocks, 128, SMEM_BYTES>>>(x, nSamples, half);

    int lblocks = ((nSamples + 1) / 2 + 127) / 128;
    lin_kernel<<<lblocks, 128>>>((float*)d_out, nSamples);
}

// round 15
// speedup vs baseline: 1.3510x; 1.0116x over previous
#include <cuda_runtime.h>

typedef unsigned long long u64;
struct uu2 { u64 a, b; };

// ---------------- merged constant blob ----------------
// linsp: [r*24+o] = (Wl[o][f(r)], same) splatted, r = t2*16+ch, f = ch*6+t2 ; then 24 splatted bl
// pack:  [0..192) w12p[(ci*3+k)*8+co] | [192..576) w21p[(ci*3+k)*16+co]
//        [576..1344) w22p[(ci*3+k)*16+co]
//        [3648..3672) w11p[k*8+co] | [3672..3680) b11 | [3680..3688) b12
//        [3688..3704) b21 | [3704..3720) b22 | [3720..3744) bl
#define LINW (96 * 24)
#define PACKN 3744
struct __align__(16) Blob {
    u64   linsp[LINW + 24];
    float pack[PACKN];
};
__device__ Blob g_blob;
__constant__ Blob c_blob;

// p2 scratch [feature r][sample]
#define MAXN 131072
__device__ float g_p2[96 * MAXN];

__device__ __forceinline__ u64 pk2(float lo, float hi) {
    u64 r; asm("mov.b64 %0,{%1,%2};" : "=l"(r) : "f"(lo), "f"(hi)); return r;
}
__device__ __forceinline__ float2 upk2(u64 v) {
    float2 f; asm("mov.b64 {%0,%1},%2;" : "=f"(f.x), "=f"(f.y) : "l"(v)); return f;
}
__device__ __forceinline__ u64 ffma2(u64 a, u64 b, u64 c) {
    u64 d; asm("fma.rn.f32x2 %0,%1,%2,%3;" : "=l"(d) : "l"(a), "l"(b), "l"(c)); return d;
}
__device__ __forceinline__ uu2 cpk4(int idx) {          // LDC.128 from pack (idx mult of 4)
    ulonglong2 v = *reinterpret_cast<const ulonglong2*>(&c_blob.pack[idx]);
    uu2 r; r.a = v.x; r.b = v.y; return r;
}

__global__ void repack_kernel(
    const float* __restrict__ w11, const float* __restrict__ b11,
    const float* __restrict__ w12, const float* __restrict__ b12,
    const float* __restrict__ w21, const float* __restrict__ b21,
    const float* __restrict__ w22, const float* __restrict__ b22,
    const float* __restrict__ Wl,  const float* __restrict__ bl)
{
    int gtid = blockIdx.x * 128 + threadIdx.x;
    int stride = gridDim.x * 128;
    for (int i = gtid; i < 192;  i += stride) g_blob.pack[i]       = w12[(i & 7)  * 24 + (i >> 3)];
    for (int i = gtid; i < 384;  i += stride) g_blob.pack[192 + i] = w21[(i & 15) * 24 + (i >> 4)];
    for (int i = gtid; i < 768;  i += stride) g_blob.pack[576 + i] = w22[(i & 15) * 48 + (i >> 4)];
    for (int i = gtid; i < 2304; i += stride) {
        int o = i % 24; int r = i / 24;
        float w = Wl[o * 96 + (r & 15) * 6 + (r >> 4)];
        g_blob.linsp[i] = pk2(w, w);
    }
    if (gtid < 24) g_blob.linsp[LINW + gtid] = pk2(bl[gtid], bl[gtid]);
    if (gtid < 24) g_blob.pack[3648 + gtid] = w11[(gtid & 7) * 3 + (gtid >> 3)];
    if (gtid < 8)  g_blob.pack[3672 + gtid] = b11[gtid];
    if (gtid < 8)  g_blob.pack[3680 + gtid] = b12[gtid];
    if (gtid < 16) g_blob.pack[3688 + gtid] = b21[gtid];
    if (gtid < 16) g_blob.pack[3704 + gtid] = b22[gtid];
    if (gtid < 24) g_blob.pack[3720 + gtid] = bl[gtid];
}

#define P1_STRIDE 128
#define SMEM_BYTES (96 * 128 * 4)

// One full sample: conv11 -> relu -> conv12 -> relu -> pool -> conv21 -> relu
//                  -> conv22 -> relu -> pool -> p2 (global).
// __noinline__: single code copy (I$-friendly), called twice straight-line from the
// kernel (no runtime loop -> ptxas keeps arrays in registers).
__device__ __noinline__ void process_sample(const float* __restrict__ x,
                                            float* __restrict__ p1s, int s, int n)
{
    // ---- input sample ----
    float xv[24];
    {
        const float4* xg = reinterpret_cast<const float4*>(x + (size_t)s * 24);
#pragma unroll
        for (int i = 0; i < 6; i++) {
            float4 v = xg[i];
            xv[4*i] = v.x; xv[4*i+1] = v.y; xv[4*i+2] = v.z; xv[4*i+3] = v.w;
        }
    }

    // ============ stage A ============
    u64 h1[4][4];                               // channel-pair packed h1 ring
    auto H1 = [&](int pos) {
        float xm = (pos > 0)  ? xv[pos - 1] : 0.f;
        float xc = xv[pos];
        float xp = (pos < 23) ? xv[pos + 1] : 0.f;
        u64 sm_ = pk2(xm, xm), sc = pk2(xc, xc), sp = pk2(xp, xp);
        u64* d = h1[pos & 3];
        uu2 b01 = cpk4(3672), b23 = cpk4(3676);
        u64 acc[4] = {b01.a, b01.b, b23.a, b23.b};
        uu2 wk0 = cpk4(3648),      wk0b = cpk4(3652);
        uu2 wk1 = cpk4(3648 + 8),  wk1b = cpk4(3648 + 12);
        uu2 wk2 = cpk4(3648 + 16), wk2b = cpk4(3648 + 20);
        acc[0] = ffma2(wk0.a,  sm_, acc[0]); acc[1] = ffma2(wk0.b,  sm_, acc[1]);
        acc[2] = ffma2(wk0b.a, sm_, acc[2]); acc[3] = ffma2(wk0b.b, sm_, acc[3]);
        acc[0] = ffma2(wk1.a,  sc,  acc[0]); acc[1] = ffma2(wk1.b,  sc,  acc[1]);
        acc[2] = ffma2(wk1b.a, sc,  acc[2]); acc[3] = ffma2(wk1b.b, sc,  acc[3]);
        acc[0] = ffma2(wk2.a,  sp,  acc[0]); acc[1] = ffma2(wk2.b,  sp,  acc[1]);
        acc[2] = ffma2(wk2b.a, sp,  acc[2]); acc[3] = ffma2(wk2b.b, sp,  acc[3]);
#pragma unroll
        for (int p = 0; p < 4; p++) {
            float2 v = upk2(acc[p]);
            d[p] = pk2(fmaxf(v.x, 0.f), fmaxf(v.y, 0.f));
        }
    };
    H1(0); H1(1); H1(2);

#pragma unroll
    for (int t = 0; t < 12; t++) {
        u64 Ae[4], Ao[4];
        {
            uu2 b01 = cpk4(3680), b23 = cpk4(3684);
            Ae[0] = b01.a; Ae[1] = b01.b; Ae[2] = b23.a; Ae[3] = b23.b;
            Ao[0] = b01.a; Ao[1] = b01.b; Ao[2] = b23.a; Ao[3] = b23.b;
        }
#pragma unroll
        for (int ci = 0; ci < 8; ci++) {
#pragma unroll
            for (int k = 0; k < 3; k++) {
                int pe = 2*t + k - 1, po = 2*t + k;
                float ge = 0.f, go = 0.f;
                if (pe >= 0) {
                    float2 v = upk2(h1[pe & 3][ci >> 1]);
                    ge = (ci & 1) ? v.y : v.x;
                }
                if (po <= 23) {
                    float2 v = upk2(h1[po & 3][ci >> 1]);
                    go = (ci & 1) ? v.y : v.x;
                }
                u64 se = pk2(ge, ge), so = pk2(go, go);
                uu2 w01 = cpk4((ci*3 + k) * 8);
                uu2 w23 = cpk4((ci*3 + k) * 8 + 4);
                Ae[0] = ffma2(w01.a, se, Ae[0]);  Ao[0] = ffma2(w01.a, so, Ao[0]);
                Ae[1] = ffma2(w01.b, se, Ae[1]);  Ao[1] = ffma2(w01.b, so, Ao[1]);
                Ae[2] = ffma2(w23.a, se, Ae[2]);  Ao[2] = ffma2(w23.a, so, Ao[2]);
                Ae[3] = ffma2(w23.b, se, Ae[3]);  Ao[3] = ffma2(w23.b, so, Ao[3]);
            }
        }
#pragma unroll
        for (int p = 0; p < 4; p++) {
            float2 e = upk2(Ae[p]), o = upk2(Ao[p]);
            p1s[((2*p)     * 12 + t) * P1_STRIDE] = fmaxf(fmaxf(e.x, o.x), 0.f);
            p1s[((2*p + 1) * 12 + t) * P1_STRIDE] = fmaxf(fmaxf(e.y, o.y), 0.f);
        }
        if (t < 11) H1(2*t + 3);
        if (t < 10) H1(2*t + 4);
    }

    // ============ stage B ============
    float r3[3][16];
    auto H3 = [&](int j) {
        u64 D[8];
#pragma unroll
        for (int h = 0; h < 4; h++) {
            uu2 b = cpk4(3688 + 4*h);
            D[2*h] = b.a; D[2*h + 1] = b.b;
        }
#pragma unroll
        for (int ci = 0; ci < 8; ci++) {
#pragma unroll
            for (int k = 0; k < 3; k++) {
                int col = j + k - 1;
                if (col >= 0 && col <= 11) {
                    float g = p1s[(ci * 12 + col) * P1_STRIDE];
                    u64 sg = pk2(g, g);
                    int wb = 192 + (ci*3 + k) * 16;
#pragma unroll
                    for (int h = 0; h < 4; h++) {
                        uu2 w = cpk4(wb + 4*h);
                        D[2*h]     = ffma2(w.a, sg, D[2*h]);
                        D[2*h + 1] = ffma2(w.b, sg, D[2*h + 1]);
                    }
                }
            }
        }
        float* o = r3[j % 3];
#pragma unroll
        for (int p = 0; p < 8; p++) {
            float2 v = upk2(D[p]);
            o[2*p] = fmaxf(v.x, 0.f); o[2*p + 1] = fmaxf(v.y, 0.f);
        }
    };

    auto C22 = [&](int pos, u64 A[8]) {
#pragma unroll
        for (int h = 0; h < 4; h++) {
            uu2 b = cpk4(3704 + 4*h);
            A[2*h] = b.a; A[2*h + 1] = b.b;
        }
#pragma unroll
        for (int ci = 0; ci < 16; ci++) {
#pragma unroll
            for (int k = 0; k < 3; k++) {
                int col = pos + k - 1;
                if (col >= 0 && col <= 11) {
                    float g = r3[col % 3][ci];
                    u64 sg = pk2(g, g);
                    int wb = 576 + (ci*3 + k) * 16;
#pragma unroll
                    for (int h = 0; h < 4; h++) {
                        uu2 w = cpk4(wb + 4*h);
                        A[2*h]     = ffma2(w.a, sg, A[2*h]);
                        A[2*h + 1] = ffma2(w.b, sg, A[2*h + 1]);
                    }
                }
            }
        }
    };

    H3(0); H3(1);
#pragma unroll
    for (int t2 = 0; t2 < 6; t2++) {
        u64 AA[8], AB[8];
        C22(2*t2, AA);
        if (2*t2 + 2 <= 11) H3(2*t2 + 2);
        C22(2*t2 + 1, AB);
#pragma unroll
        for (int p = 0; p < 8; p++) {
            float2 a = upk2(AA[p]), b = upk2(AB[p]);
            g_p2[(size_t)(t2 * 16 + 2*p)     * n + s] = fmaxf(fmaxf(a.x, b.x), 0.f);
            g_p2[(size_t)(t2 * 16 + 2*p + 1) * n + s] = fmaxf(fmaxf(a.y, b.y), 0.f);
        }
        if (2*t2 + 3 <= 11) H3(2*t2 + 3);
    }
}

// half-grid single wave: thread handles sample s, then s+half, via two straight-line
// calls to the (single-copy) __noinline__ body.
__global__ void __launch_bounds__(128, 4)
cnn_main(const float* __restrict__ x, int n, int half)
{
    extern __shared__ float p1s_base[];
    float* p1s = p1s_base + threadIdx.x;

    int s = blockIdx.x * 128 + threadIdx.x;
    if (s >= half) return;
    process_sample(x, p1s, s, n);
    process_sample(x, p1s, s + half, n);     // half*2 >= n and s < half => s+half < n
}

// ============ linear: 2 adjacent samples per thread, samples in f32x2 lanes ==========
// 64-thread blocks -> 2x the CTAs for this latency-bound kernel.
__global__ void __launch_bounds__(64)
lin_kernel(float* __restrict__ out, int n)
{
    int i = blockIdx.x * 64 + threadIdx.x;
    int s0 = 2 * i;
    if (s0 + 1 >= n) {                   // n even in practice; cheap guard for odd tails
        if (s0 < n) {
            float acc[24];
#pragma unroll
            for (int o = 0; o < 24; o++) acc[o] = upk2(c_blob.linsp[LINW + o]).x;
            for (int r = 0; r < 96; r++) {
                float v = g_p2[(size_t)r * n + s0];
#pragma unroll
                for (int o = 0; o < 24; o++)
                    acc[o] = fmaf(upk2(c_blob.linsp[r*24 + o]).x, v, acc[o]);
            }
#pragma unroll
            for (int o = 0; o < 24; o++) out[(size_t)s0 * 24 + o] = acc[o];
        }
        return;
    }

    u64 acc[24];
#pragma unroll
    for (int o = 0; o < 24; o++) acc[o] = c_blob.linsp[LINW + o];

#pragma unroll 8
    for (int r = 0; r < 96; r++) {
        float2 v = *reinterpret_cast<const float2*>(&g_p2[(size_t)r * n + s0]);
        u64 pv = pk2(v.x, v.y);
        const u64* w = &c_blob.linsp[r * 24];
#pragma unroll
        for (int h = 0; h < 12; h++) {
            ulonglong2 w2 = *reinterpret_cast<const ulonglong2*>(&w[2*h]);
            acc[2*h]     = ffma2(w2.x, pv, acc[2*h]);
            acc[2*h + 1] = ffma2(w2.y, pv, acc[2*h + 1]);
        }
    }
    float rA[24], rB[24];
#pragma unroll
    for (int o = 0; o < 24; o++) {
        float2 v = upk2(acc[o]);
        rA[o] = v.x; rB[o] = v.y;
    }
    float4* oA = reinterpret_cast<float4*>(out + (size_t)s0 * 24);
    float4* oB = reinterpret_cast<float4*>(out + (size_t)(s0 + 1) * 24);
#pragma unroll
    for (int q = 0; q < 6; q++) {
        oA[q] = make_float4(rA[4*q], rA[4*q+1], rA[4*q+2], rA[4*q+3]);
        oB[q] = make_float4(rB[4*q], rB[4*q+1], rB[4*q+2], rB[4*q+3]);
    }
}

extern "C" void kernel_launch(void* const* d_in, const int* in_sizes, int n_in,
                              void* d_out, int out_size)
{
    const float* x = (const float*)d_in[0];

    repack_kernel<<<32, 128>>>(
        (const float*)d_in[1], (const float*)d_in[2],
        (const float*)d_in[3], (const float*)d_in[4],
        (const float*)d_in[5], (const float*)d_in[6],
        (const float*)d_in[7], (const float*)d_in[8],
        (const float*)d_in[9], (const float*)d_in[10]);

    void *cb, *gb;
    cudaGetSymbolAddress(&cb, c_blob);
    cudaGetSymbolAddress(&gb, g_blob);
    cudaMemcpyAsync(cb, gb, sizeof(Blob), cudaMemcpyDeviceToDevice, 0);

    static bool attr_set = false;
    if (!attr_set) {
        cudaFuncSetAttribute(cnn_main,
                             cudaFuncAttributeMaxDynamicSharedMemorySize, SMEM_BYTES);
        attr_set = true;
    }

    int nSamples = in_sizes[0] / 24;            // 512*256 = 131072 (<= MAXN)
    int half = (nSamples + 1) / 2;
    int mblocks = (half + 127) / 128;           // 512 blocks -> single resident wave
    cnn_main<<<mblocks, 128, SMEM_BYTES>>>(x, nSamples, half);

    int lblocks = ((nSamples + 1) / 2 + 63) / 64;
    lin_kernel<<<lblocks, 64>>>((float*)d_out, nSamples);
}

// round 16
// speedup vs baseline: 1.3736x; 1.0167x over previous
#include <cuda_runtime.h>

typedef unsigned long long u64;
struct uu2 { u64 a, b; };

// ---------------- merged constant blob (written DIRECTLY by repack kernel) ----------------
// linsp: [r*24+o] = (Wl[o][f(r)], same) splatted, r = t2*16+ch, f = ch*6+t2 ; then 24 splatted bl
// pack:  [0..192) w12p[(ci*3+k)*8+co] | [192..576) w21p[(ci*3+k)*16+co]
//        [576..1344) w22p[(ci*3+k)*16+co]
//        [3648..3672) w11p[k*8+co] | [3672..3680) b11 | [3680..3688) b12
//        [3688..3704) b21 | [3704..3720) b22 | [3720..3744) bl
#define LINW (96 * 24)
#define PACKN 3744
struct __align__(16) Blob {
    u64   linsp[LINW + 24];
    float pack[PACKN];
};
__constant__ Blob c_blob;

// p2 scratch [feature r][sample]
#define MAXN 131072
__device__ float g_p2[96 * MAXN];

__device__ __forceinline__ u64 pk2(float lo, float hi) {
    u64 r; asm("mov.b64 %0,{%1,%2};" : "=l"(r) : "f"(lo), "f"(hi)); return r;
}
__device__ __forceinline__ float2 upk2(u64 v) {
    float2 f; asm("mov.b64 {%0,%1},%2;" : "=f"(f.x), "=f"(f.y) : "l"(v)); return f;
}
__device__ __forceinline__ u64 ffma2(u64 a, u64 b, u64 c) {
    u64 d; asm("fma.rn.f32x2 %0,%1,%2,%3;" : "=l"(d) : "l"(a), "l"(b), "l"(c)); return d;
}
__device__ __forceinline__ uu2 cpk4(int idx) {          // LDC.128 from pack (idx mult of 4)
    ulonglong2 v = *reinterpret_cast<const ulonglong2*>(&c_blob.pack[idx]);
    uu2 r; r.a = v.x; r.b = v.y; return r;
}

// writes straight into the constant bank's backing store (dst = &c_blob, device address).
// Launch-boundary cache flush makes the new values visible to subsequent kernels' LDC.
__global__ void repack_kernel(Blob* __restrict__ dst,
    const float* __restrict__ w11, const float* __restrict__ b11,
    const float* __restrict__ w12, const float* __restrict__ b12,
    const float* __restrict__ w21, const float* __restrict__ b21,
    const float* __restrict__ w22, const float* __restrict__ b22,
    const float* __restrict__ Wl,  const float* __restrict__ bl)
{
    int gtid = blockIdx.x * 128 + threadIdx.x;
    int stride = gridDim.x * 128;
    for (int i = gtid; i < 192;  i += stride) dst->pack[i]       = w12[(i & 7)  * 24 + (i >> 3)];
    for (int i = gtid; i < 384;  i += stride) dst->pack[192 + i] = w21[(i & 15) * 24 + (i >> 4)];
    for (int i = gtid; i < 768;  i += stride) dst->pack[576 + i] = w22[(i & 15) * 48 + (i >> 4)];
    for (int i = gtid; i < 2304; i += stride) {
        int o = i % 24; int r = i / 24;
        float w = Wl[o * 96 + (r & 15) * 6 + (r >> 4)];
        dst->linsp[i] = pk2(w, w);
    }
    if (gtid < 24) dst->linsp[LINW + gtid] = pk2(bl[gtid], bl[gtid]);
    if (gtid < 24) dst->pack[3648 + gtid] = w11[(gtid & 7) * 3 + (gtid >> 3)];
    if (gtid < 8)  dst->pack[3672 + gtid] = b11[gtid];
    if (gtid < 8)  dst->pack[3680 + gtid] = b12[gtid];
    if (gtid < 16) dst->pack[3688 + gtid] = b21[gtid];
    if (gtid < 16) dst->pack[3704 + gtid] = b22[gtid];
    if (gtid < 24) dst->pack[3720 + gtid] = bl[gtid];
}

#define P1_STRIDE 128
#define SMEM_BYTES (96 * 128 * 4)

// One full sample: conv11 -> relu -> conv12 -> relu -> pool -> conv21 -> relu
//                  -> conv22 -> relu -> pool -> p2 (global).
// __noinline__: single code copy (I$-friendly), called twice straight-line from the
// kernel (no runtime loop -> ptxas keeps arrays in registers).
__device__ __noinline__ void process_sample(const float* __restrict__ x,
                                            float* __restrict__ p1s, int s, int n)
{
    // ---- input sample ----
    float xv[24];
    {
        const float4* xg = reinterpret_cast<const float4*>(x + (size_t)s * 24);
#pragma unroll
        for (int i = 0; i < 6; i++) {
            float4 v = xg[i];
            xv[4*i] = v.x; xv[4*i+1] = v.y; xv[4*i+2] = v.z; xv[4*i+3] = v.w;
        }
    }

    // ============ stage A ============
    u64 h1[4][4];                               // channel-pair packed h1 ring
    auto H1 = [&](int pos) {
        float xm = (pos > 0)  ? xv[pos - 1] : 0.f;
        float xc = xv[pos];
        float xp = (pos < 23) ? xv[pos + 1] : 0.f;
        u64 sm_ = pk2(xm, xm), sc = pk2(xc, xc), sp = pk2(xp, xp);
        u64* d = h1[pos & 3];
        uu2 b01 = cpk4(3672), b23 = cpk4(3676);
        u64 acc[4] = {b01.a, b01.b, b23.a, b23.b};
        uu2 wk0 = cpk4(3648),      wk0b = cpk4(3652);
        uu2 wk1 = cpk4(3648 + 8),  wk1b = cpk4(3648 + 12);
        uu2 wk2 = cpk4(3648 + 16), wk2b = cpk4(3648 + 20);
        acc[0] = ffma2(wk0.a,  sm_, acc[0]); acc[1] = ffma2(wk0.b,  sm_, acc[1]);
        acc[2] = ffma2(wk0b.a, sm_, acc[2]); acc[3] = ffma2(wk0b.b, sm_, acc[3]);
        acc[0] = ffma2(wk1.a,  sc,  acc[0]); acc[1] = ffma2(wk1.b,  sc,  acc[1]);
        acc[2] = ffma2(wk1b.a, sc,  acc[2]); acc[3] = ffma2(wk1b.b, sc,  acc[3]);
        acc[0] = ffma2(wk2.a,  sp,  acc[0]); acc[1] = ffma2(wk2.b,  sp,  acc[1]);
        acc[2] = ffma2(wk2b.a, sp,  acc[2]); acc[3] = ffma2(wk2b.b, sp,  acc[3]);
#pragma unroll
        for (int p = 0; p < 4; p++) {
            float2 v = upk2(acc[p]);
            d[p] = pk2(fmaxf(v.x, 0.f), fmaxf(v.y, 0.f));
        }
    };
    H1(0); H1(1); H1(2);

#pragma unroll
    for (int t = 0; t < 12; t++) {
        u64 Ae[4], Ao[4];
        {
            uu2 b01 = cpk4(3680), b23 = cpk4(3684);
            Ae[0] = b01.a; Ae[1] = b01.b; Ae[2] = b23.a; Ae[3] = b23.b;
            Ao[0] = b01.a; Ao[1] = b01.b; Ao[2] = b23.a; Ao[3] = b23.b;
        }
#pragma unroll
        for (int ci = 0; ci < 8; ci++) {
#pragma unroll
            for (int k = 0; k < 3; k++) {
                int pe = 2*t + k - 1, po = 2*t + k;
                float ge = 0.f, go = 0.f;
                if (pe >= 0) {
                    float2 v = upk2(h1[pe & 3][ci >> 1]);
                    ge = (ci & 1) ? v.y : v.x;
                }
                if (po <= 23) {
                    float2 v = upk2(h1[po & 3][ci >> 1]);
                    go = (ci & 1) ? v.y : v.x;
                }
                u64 se = pk2(ge, ge), so = pk2(go, go);
                uu2 w01 = cpk4((ci*3 + k) * 8);
                uu2 w23 = cpk4((ci*3 + k) * 8 + 4);
                Ae[0] = ffma2(w01.a, se, Ae[0]);  Ao[0] = ffma2(w01.a, so, Ao[0]);
                Ae[1] = ffma2(w01.b, se, Ae[1]);  Ao[1] = ffma2(w01.b, so, Ao[1]);
                Ae[2] = ffma2(w23.a, se, Ae[2]);  Ao[2] = ffma2(w23.a, so, Ao[2]);
                Ae[3] = ffma2(w23.b, se, Ae[3]);  Ao[3] = ffma2(w23.b, so, Ao[3]);
            }
        }
#pragma unroll
        for (int p = 0; p < 4; p++) {
            float2 e = upk2(Ae[p]), o = upk2(Ao[p]);
            p1s[((2*p)     * 12 + t) * P1_STRIDE] = fmaxf(fmaxf(e.x, o.x), 0.f);
            p1s[((2*p + 1) * 12 + t) * P1_STRIDE] = fmaxf(fmaxf(e.y, o.y), 0.f);
        }
        if (t < 11) H1(2*t + 3);
        if (t < 10) H1(2*t + 4);
    }

    // ============ stage B ============
    float r3[3][16];
    auto H3 = [&](int j) {
        u64 D[8];
#pragma unroll
        for (int h = 0; h < 4; h++) {
            uu2 b = cpk4(3688 + 4*h);
            D[2*h] = b.a; D[2*h + 1] = b.b;
        }
#pragma unroll
        for (int ci = 0; ci < 8; ci++) {
#pragma unroll
            for (int k = 0; k < 3; k++) {
                int col = j + k - 1;
                if (col >= 0 && col <= 11) {
                    float g = p1s[(ci * 12 + col) * P1_STRIDE];
                    u64 sg = pk2(g, g);
                    int wb = 192 + (ci*3 + k) * 16;
#pragma unroll
                    for (int h = 0; h < 4; h++) {
                        uu2 w = cpk4(wb + 4*h);
                        D[2*h]     = ffma2(w.a, sg, D[2*h]);
                        D[2*h + 1] = ffma2(w.b, sg, D[2*h + 1]);
                    }
                }
            }
        }
        float* o = r3[j % 3];
#pragma unroll
        for (int p = 0; p < 8; p++) {
            float2 v = upk2(D[p]);
            o[2*p] = fmaxf(v.x, 0.f); o[2*p + 1] = fmaxf(v.y, 0.f);
        }
    };

    auto C22 = [&](int pos, u64 A[8]) {
#pragma unroll
        for (int h = 0; h < 4; h++) {
            uu2 b = cpk4(3704 + 4*h);
            A[2*h] = b.a; A[2*h + 1] = b.b;
        }
#pragma unroll
        for (int ci = 0; ci < 16; ci++) {
#pragma unroll
            for (int k = 0; k < 3; k++) {
                int col = pos + k - 1;
                if (col >= 0 && col <= 11) {
                    float g = r3[col % 3][ci];
                    u64 sg = pk2(g, g);
                    int wb = 576 + (ci*3 + k) * 16;
#pragma unroll
                    for (int h = 0; h < 4; h++) {
                        uu2 w = cpk4(wb + 4*h);
                        A[2*h]     = ffma2(w.a, sg, A[2*h]);
                        A[2*h + 1] = ffma2(w.b, sg, A[2*h + 1]);
                    }
                }
            }
        }
    };

    H3(0); H3(1);
#pragma unroll
    for (int t2 = 0; t2 < 6; t2++) {
        u64 AA[8], AB[8];
        C22(2*t2, AA);
        if (2*t2 + 2 <= 11) H3(2*t2 + 2);
        C22(2*t2 + 1, AB);
#pragma unroll
        for (int p = 0; p < 8; p++) {
            float2 a = upk2(AA[p]), b = upk2(AB[p]);
            g_p2[(size_t)(t2 * 16 + 2*p)     * n + s] = fmaxf(fmaxf(a.x, b.x), 0.f);
            g_p2[(size_t)(t2 * 16 + 2*p + 1) * n + s] = fmaxf(fmaxf(a.y, b.y), 0.f);
        }
        if (2*t2 + 3 <= 11) H3(2*t2 + 3);
    }
}

// half-grid single wave: thread handles sample s, then s+half, via two straight-line
// calls to the (single-copy) __noinline__ body.
__global__ void __launch_bounds__(128, 4)
cnn_main(const float* __restrict__ x, int n, int half)
{
    extern __shared__ float p1s_base[];
    float* p1s = p1s_base + threadIdx.x;

    int s = blockIdx.x * 128 + threadIdx.x;
    if (s >= half) return;
    process_sample(x, p1s, s, n);
    process_sample(x, p1s, s + half, n);     // half*2 >= n and s < half => s+half < n
}

// ============ linear: 2 adjacent samples per thread, samples in f32x2 lanes ==========
// 64-thread blocks -> more resident CTAs for this latency-bound kernel.
__global__ void __launch_bounds__(64)
lin_kernel(float* __restrict__ out, int n)
{
    int i = blockIdx.x * 64 + threadIdx.x;
    int s0 = 2 * i;
    if (s0 + 1 >= n) {                   // n even in practice; cheap guard for odd tails
        if (s0 < n) {
            float acc[24];
#pragma unroll
            for (int o = 0; o < 24; o++) acc[o] = upk2(c_blob.linsp[LINW + o]).x;
            for (int r = 0; r < 96; r++) {
                float v = g_p2[(size_t)r * n + s0];
#pragma unroll
                for (int o = 0; o < 24; o++)
                    acc[o] = fmaf(upk2(c_blob.linsp[r*24 + o]).x, v, acc[o]);
            }
#pragma unroll
            for (int o = 0; o < 24; o++) out[(size_t)s0 * 24 + o] = acc[o];
        }
        return;
    }

    u64 acc[24];
#pragma unroll
    for (int o = 0; o < 24; o++) acc[o] = c_blob.linsp[LINW + o];

#pragma unroll 8
    for (int r = 0; r < 96; r++) {
        float2 v = *reinterpret_cast<const float2*>(&g_p2[(size_t)r * n + s0]);
        u64 pv = pk2(v.x, v.y);
        const u64* w = &c_blob.linsp[r * 24];
#pragma unroll
        for (int h = 0; h < 12; h++) {
            ulonglong2 w2 = *reinterpret_cast<const ulonglong2*>(&w[2*h]);
            acc[2*h]     = ffma2(w2.x, pv, acc[2*h]);
            acc[2*h + 1] = ffma2(w2.y, pv, acc[2*h + 1]);
        }
    }
    float rA[24], rB[24];
#pragma unroll
    for (int o = 0; o < 24; o++) {
        float2 v = upk2(acc[o]);
        rA[o] = v.x; rB[o] = v.y;
    }
    float4* oA = reinterpret_cast<float4*>(out + (size_t)s0 * 24);
    float4* oB = reinterpret_cast<float4*>(out + (size_t)(s0 + 1) * 24);
#pragma unroll
    for (int q = 0; q < 6; q++) {
        oA[q] = make_float4(rA[4*q], rA[4*q+1], rA[4*q+2], rA[4*q+3]);
        oB[q] = make_float4(rB[4*q], rB[4*q+1], rB[4*q+2], rB[4*q+3]);
    }
}

extern "C" void kernel_launch(void* const* d_in, const int* in_sizes, int n_in,
                              void* d_out, int out_size)
{
    const float* x = (const float*)d_in[0];

    // device address of the constant blob's backing store — repack writes it directly
    void* cb = nullptr;
    cudaGetSymbolAddress(&cb, c_blob);

    repack_kernel<<<32, 128>>>((Blob*)cb,
        (const float*)d_in[1], (const float*)d_in[2],
        (const float*)d_in[3], (const float*)d_in[4],
        (const float*)d_in[5], (const float*)d_in[6],
        (const float*)d_in[7], (const float*)d_in[8],
        (const float*)d_in[9], (const float*)d_in[10]);

    static bool attr_set = false;
    if (!attr_set) {
        cudaFuncSetAttribute(cnn_main,
                             cudaFuncAttributeMaxDynamicSharedMemorySize, SMEM_BYTES);
        attr_set = true;
    }

    int nSamples = in_sizes[0] / 24;            // 512*256 = 131072 (<= MAXN)
    int half = (nSamples + 1) / 2;
    int mblocks = (half + 127) / 128;           // 512 blocks -> single resident wave
    cnn_main<<<mblocks, 128, SMEM_BYTES>>>(x, nSamples, half);

    int lblocks = ((nSamples + 1) / 2 + 63) / 64;
    lin_kernel<<<lblocks, 64>>>((float*)d_out, nSamples);
}